// round 3
// baseline (speedup 1.0000x reference)
#include <cuda_runtime.h>

// OrthonormalWaveletRegularization: L=32 -> scalar.
// One warp, zero shared memory, zero tables: lane-per-element layout,
// all 34 partial sums reduced in one batched 5-stage butterfly.
// (R2's divergent constant-bank LDC replays were the 8.5us bottleneck.)

#define SQRT2D 1.41421356237309504880

__global__ void owr_kernel(const float* __restrict__ h,
                           const float* __restrict__ g,
                           float* __restrict__ out) {
    const int t = threadIdx.x;            // lane = element index r
    const float hv = h[t];
    const float gv = g[t];

    // v[0]=sum h, v[1]=sum g, v[2]=dot(h,h)
    // v[3..17]   : autocorr products for lags d=2k, k=1..15
    // v[18..33]  : moment terms w*g_r for p=1..16 (w = r^(p-1))
    float v[34];
    v[0] = hv;
    v[1] = gv;
    v[2] = hv * hv;

    #pragma unroll
    for (int k = 1; k <= 15; ++k) {
        const int d = 2 * k;
        const float hshift = __shfl_down_sync(0xFFFFFFFFu, hv, d);
        v[2 + k] = (t + d < 32) ? hv * hshift : 0.0f;
    }

    {
        const float rf = (float)t;
        float w = 1.0f;                   // r^0 = 1 (incl. 0^0, matches numpy)
        #pragma unroll
        for (int p = 1; p <= 16; ++p) {
            v[17 + p] = w * gv;
            w *= rf;
        }
    }

    // One batched butterfly: 34 independent reduction chains, 5 stages.
    #pragma unroll
    for (int o = 16; o > 0; o >>= 1) {
        #pragma unroll
        for (int j = 0; j < 34; ++j)
            v[j] += __shfl_xor_sync(0xFFFFFFFFu, v[j], o);
    }

    if (t == 0) {
        const double l1 = ((double)v[0] - SQRT2D) * ((double)v[0] - SQRT2D);
        const double l2 = (double)v[1] * (double)v[1];
        const double l3 = ((double)v[2] - 1.0) * ((double)v[2] - 1.0);

        double l4 = 0.0;
        #pragma unroll
        for (int k = 1; k <= 15; ++k)
            l4 += (double)v[2 + k] * (double)v[2 + k];

        // norm_p^2 = (sqrt2 / 2^p)^2 = 2^(1-2p)  (exact powers of two)
        double l5 = 0.0;
        #pragma unroll
        for (int p = 1; p <= 16; ++p) {
            const double m = (double)v[17 + p];
            // ldexp with compile-time exponent folds to a constant multiply
            l5 += m * m * ldexp(1.0, 1 - 2 * p);
        }

        out[0] = (float)((l1 + l2) + (l3 + l4) + l5);
    }
}

extern "C" void kernel_launch(void* const* d_in, const int* in_sizes, int n_in,
                              void* d_out, int out_size) {
    const float* h = (const float*)d_in[0];
    const float* g = (const float*)d_in[1];
    float* out = (float*)d_out;
    owr_kernel<<<1, 32>>>(h, g, out);
}

// round 4
// speedup vs baseline: 1.6000x; 1.6000x over previous
#include <cuda_runtime.h>

// OrthonormalWaveletRegularization: L=32 -> scalar. One warp, all-fp32.
// R4: smem-transpose reduction (35 SHFL total, zero FP64) replacing R3's
// 185-SHFL butterfly + serial double tail.

#define SQRT2F 1.41421356237309504880f

__global__ void owr_kernel(const float* __restrict__ h,
                           const float* __restrict__ g,
                           float* __restrict__ out) {
    const int t = threadIdx.x;              // lane = element index r
    __shared__ float s[31][33];             // stride 33: conflict-free both ways

    const float hv = h[t];
    const float gv = g[t];

    // --- per-lane partials ---
    // chains 0..14: lag products h[r]*h[r+2k], k=1..15
    #pragma unroll
    for (int k = 1; k <= 15; ++k) {
        const int d = 2 * k;
        const float hs = __shfl_down_sync(0xFFFFFFFFu, hv, d);
        s[k - 1][t] = (t + d < 32) ? hv * hs : 0.0f;
    }
    // chains 15..30: moment terms r^(p-1)*g[r], p=1..16 (0^0=1 via w init)
    {
        float w = 1.0f;
        const float rf = (float)t;
        #pragma unroll
        for (int p = 1; p <= 16; ++p) {
            s[14 + p][t] = w * gv;
            w *= rf;
        }
    }

    // --- small butterfly for the 3 plain sums (needed by lane 31) ---
    float s_h = hv, s_g = gv, s_hh = hv * hv;
    #pragma unroll
    for (int o = 16; o > 0; o >>= 1) {
        s_h  += __shfl_xor_sync(0xFFFFFFFFu, s_h,  o);
        s_g  += __shfl_xor_sync(0xFFFFFFFFu, s_g,  o);
        s_hh += __shfl_xor_sync(0xFFFFFFFFu, s_hh, o);
    }

    __syncwarp();

    // --- transpose: lane j tree-sums chain j, then squares/scales locally ---
    float contrib;
    if (t < 31) {
        float x[32];
        #pragma unroll
        for (int i = 0; i < 32; ++i)
            x[i] = s[t][i];                 // bank (t+i)%32: conflict-free
        #pragma unroll
        for (int st = 16; st >= 1; st >>= 1)
            #pragma unroll
            for (int i = 0; i < st; ++i)
                x[i] += x[i + st];
        const float ssum = x[0];

        if (t < 15) {
            contrib = ssum * ssum;                          // l4 term
        } else {
            const int p = t - 14;                           // 1..16
            // norm = sqrt2 * 2^-p  (2^-p built from bits; p<=16 -> normal)
            const float norm = SQRT2F * __int_as_float((127 - p) << 23);
            const float m = ssum * norm;                    // scale BEFORE square
            contrib = m * m;                                // l5 term (~4e35 max, safe)
        }
    } else {
        const float e1 = s_h - SQRT2F;
        const float e3 = s_hh - 1.0f;
        contrib = e1 * e1 + s_g * s_g + e3 * e3;            // l1+l2+l3
    }

    // --- final 5-stage butterfly over 32 per-lane contributions ---
    #pragma unroll
    for (int o = 16; o > 0; o >>= 1)
        contrib += __shfl_xor_sync(0xFFFFFFFFu, contrib, o);

    if (t == 0)
        out[0] = contrib;
}

extern "C" void kernel_launch(void* const* d_in, const int* in_sizes, int n_in,
                              void* d_out, int out_size) {
    const float* h = (const float*)d_in[0];
    const float* g = (const float*)d_in[1];
    float* out = (float*)d_out;
    owr_kernel<<<1, 32>>>(h, g, out);
}

// round 5
// speedup vs baseline: 2.4056x; 1.5035x over previous
#include <cuda_runtime.h>

// OrthonormalWaveletRegularization: L=32 -> scalar. One warp, all-fp32.
// R5: everything is a smem-transpose chain (33 chains: 15 lag, 16 moment,
// h, h^2; sum(g) == p=1 moment chain). No 3-sum butterfly, log-depth
// powers, vectorized LDS.128 transpose reads.

#define SQRT2F 1.41421356237309504880f

__global__ void owr_kernel(const float* __restrict__ h,
                           const float* __restrict__ g,
                           float* __restrict__ out) {
    const int t = threadIdx.x;                       // lane = element index r
    __shared__ __align__(16) float s[33][36];        // stride 36: 16B-aligned rows

    const float hv = h[t];
    const float gv = g[t];

    // --- moment chains p=1..16 (rows 15..30): r^(p-1)*g[r], log-depth powers ---
    {
        const float r1 = (float)t;
        const float r2 = r1 * r1;
        const float r4 = r2 * r2;
        const float r8 = r4 * r4;
        float w[16];
        w[0]  = 1.0f;        w[1]  = r1;          w[2]  = r2;          w[3]  = r2 * r1;
        w[4]  = r4;          w[5]  = r4 * r1;     w[6]  = r4 * r2;     w[7]  = w[6] * r1;
        w[8]  = r8;          w[9]  = r8 * r1;     w[10] = r8 * r2;     w[11] = w[10] * r1;
        w[12] = r8 * r4;     w[13] = w[12] * r1;  w[14] = w[12] * r2;  w[15] = w[14] * r1;
        #pragma unroll
        for (int p = 1; p <= 16; ++p)
            s[14 + p][t] = w[p - 1] * gv;
    }

    // --- lag chains k=1..15 (rows 0..14): h[r]*h[r+2k] ---
    #pragma unroll
    for (int k = 1; k <= 15; ++k) {
        const int d = 2 * k;
        const float hs = __shfl_down_sync(0xFFFFFFFFu, hv, d);
        s[k - 1][t] = (t + d < 32) ? hv * hs : 0.0f;
    }

    // --- plain-sum chains: row 31 = h, row 32 = h^2 ---
    s[31][t] = hv;
    s[32][t] = hv * hv;

    __syncwarp();

    // --- transpose: lane j tree-sums chain j (lane 0 also chain 32) ---
    float sums[2];
    const int nchain = (t == 0) ? 2 : 1;
    #pragma unroll
    for (int c = 0; c < 2; ++c) {
        if (c < nchain) {
            const int chain = (c == 0) ? t : 32;
            const float4* row = (const float4*)s[chain];
            float x[8];
            #pragma unroll
            for (int i = 0; i < 8; ++i) {
                const float4 q = row[i];
                x[i] = (q.x + q.y) + (q.z + q.w);
            }
            sums[c] = ((x[0] + x[1]) + (x[2] + x[3])) + ((x[4] + x[5]) + (x[6] + x[7]));
        }
    }

    // --- per-lane contribution ---
    float contrib;
    const float ssum = sums[0];
    if (t < 15) {
        contrib = ssum * ssum;                                   // l4 term (lag k=t+1)
    } else if (t < 31) {
        const int p = t - 14;                                    // 1..16
        if (p == 1) {
            contrib = 1.5f * ssum * ssum;                        // l2 + p=1 l5 term
        } else {
            const float norm = SQRT2F * __int_as_float((127 - p) << 23); // sqrt2*2^-p
            const float m = ssum * norm;
            contrib = m * m;                                     // l5 term
        }
    } else {
        const float e1 = ssum - SQRT2F;                          // chain 31 = sum h
        contrib = e1 * e1;                                       // l1
    }
    if (t == 0) {
        const float e3 = sums[1] - 1.0f;                         // chain 32 = sum h^2
        contrib += e3 * e3;                                      // l3
    }

    // --- final 5-stage butterfly ---
    #pragma unroll
    for (int o = 16; o > 0; o >>= 1)
        contrib += __shfl_xor_sync(0xFFFFFFFFu, contrib, o);

    if (t == 0)
        out[0] = contrib;
}

extern "C" void kernel_launch(void* const* d_in, const int* in_sizes, int n_in,
                              void* d_out, int out_size) {
    const float* h = (const float*)d_in[0];
    const float* g = (const float*)d_in[1];
    float* out = (float*)d_out;
    owr_kernel<<<1, 32>>>(h, g, out);
}